// round 1
// baseline (speedup 1.0000x reference)
#include <cuda_runtime.h>
#include <cuda_bf16.h>
#include <cstdint>

// GeluAvgEmbed: out[cell] = dot(gelu(mean_t W_embed[x[cell,t]]), w_pred) + b_pred
// B,R,C,T = 8,100,64,32 ; D = 128 ; VOCAB = 32000
// One warp per cell. Lane l owns dims [4l, 4l+4). Token indices distributed
// one-per-lane and broadcast via shfl. W_embed (16.4 MB) lives in L2.

#define TOKENS 32
#define DIMS   128
#define FULL_MASK 0xffffffffu

__global__ __launch_bounds__(256) void gelu_avg_embed_kernel(
    const int*   __restrict__ x,        // [n_cells * 32]
    const float* __restrict__ W,        // [32000, 128]
    const float* __restrict__ w_pred,   // [128]
    const float* __restrict__ b_pred,   // [1]
    float*       __restrict__ out,      // [n_cells]
    int n_cells)
{
    const int gwarp = (blockIdx.x * blockDim.x + threadIdx.x) >> 5;
    const int lane  = threadIdx.x & 31;
    if (gwarp >= n_cells) return;

    // Lane t holds token t's vocab index for this cell (coalesced 128B load).
    const int my_idx = x[gwarp * TOKENS + lane];

    float4 acc = make_float4(0.f, 0.f, 0.f, 0.f);

    #pragma unroll
    for (int t = 0; t < TOKENS; ++t) {
        const int row = __shfl_sync(FULL_MASK, my_idx, t);
        const float4 v = *reinterpret_cast<const float4*>(
            W + (size_t)row * DIMS + lane * 4);
        acc.x += v.x; acc.y += v.y; acc.z += v.z; acc.w += v.w;
    }

    // Mean over tokens
    const float inv_t = 1.0f / (float)TOKENS;
    float p0 = acc.x * inv_t;
    float p1 = acc.y * inv_t;
    float p2 = acc.z * inv_t;
    float p3 = acc.w * inv_t;

    // Exact (erf) GELU
    const float kInvSqrt2 = 0.70710678118654752440f;
    float g0 = 0.5f * p0 * (1.0f + erff(p0 * kInvSqrt2));
    float g1 = 0.5f * p1 * (1.0f + erff(p1 * kInvSqrt2));
    float g2 = 0.5f * p2 * (1.0f + erff(p2 * kInvSqrt2));
    float g3 = 0.5f * p3 * (1.0f + erff(p3 * kInvSqrt2));

    // Dot with w_pred (lane's 4 dims)
    const float4 wv = *reinterpret_cast<const float4*>(w_pred + lane * 4);
    float dot = g0 * wv.x + g1 * wv.y + g2 * wv.z + g3 * wv.w;

    // Warp reduction
    #pragma unroll
    for (int off = 16; off > 0; off >>= 1)
        dot += __shfl_down_sync(FULL_MASK, dot, off);

    if (lane == 0)
        out[gwarp] = dot + b_pred[0];
}

extern "C" void kernel_launch(void* const* d_in, const int* in_sizes, int n_in,
                              void* d_out, int out_size)
{
    const int*   x      = (const int*)  d_in[0];  // [8,100,64,32] int32
    const float* W      = (const float*)d_in[1];  // [32000,128]  f32
    const float* w_pred = (const float*)d_in[2];  // [1,128]      f32
    const float* b_pred = (const float*)d_in[3];  // [1]          f32
    float*       out    = (float*)d_out;          // [8,100,64]   f32

    const int n_cells = out_size;                  // 51200
    const int warps_per_block = 8;                 // 256 threads
    const int blocks = (n_cells + warps_per_block - 1) / warps_per_block;

    gelu_avg_embed_kernel<<<blocks, 256>>>(x, W, w_pred, b_pred, out, n_cells);
}